// round 10
// baseline (speedup 1.0000x reference)
#include <cuda_runtime.h>
#include <math.h>

// Problem constants
#define TOK   4096   // B*L = 2*2048
#define DIMK  1024
#define HQ    16
#define HKV   4
#define HD    64
#define LSEQ  2048

// Scratch (static device globals — allocation-free)
__device__ float g_q [TOK * HQ  * HD];   // 16 MB  [token][h*64+d]
__device__ float g_k [TOK * HKV * HD];   //  4 MB  [token][kv*64+d]
__device__ float g_v [TOK * HKV * HD];   //  4 MB
__device__ float g_ao[TOK * HQ  * HD];   // 16 MB  attention output

// ---------------------------------------------------------------------------
// 128x128 tile SGEMM body, C[m,n] = sum_k A[m,k]*B[n,k]  (NT, both row-major,
// K contiguous). BK=16, 256 threads, 8x8 per thread with 4+4 split fragments.
// Requires: M,N tiles exactly 128, K % 16 == 0. No bounds checks needed here.
// ---------------------------------------------------------------------------
__device__ __forceinline__ void gemm128(const float* __restrict__ Ag,   // A + bm*K
                                        const float* __restrict__ Bg,   // B + bn*K
                                        float*       __restrict__ Cg,   // C + bm*ldc + bn
                                        int K, int ldc)
{
    __shared__ float As[16][128];
    __shared__ float Bs[16][128];

    const int tid  = threadIdx.x;       // 0..255
    const int lrow = tid >> 2;          // 0..63
    const int lseg = (tid & 3) << 2;    // 0,4,8,12
    const int tx   = tid & 15;
    const int ty   = tid >> 4;

    float acc[8][8];
#pragma unroll
    for (int i = 0; i < 8; i++)
#pragma unroll
        for (int j = 0; j < 8; j++) acc[i][j] = 0.0f;

    const float* A0 = Ag + (size_t)lrow        * K + lseg;
    const float* A1 = Ag + (size_t)(lrow + 64) * K + lseg;
    const float* B0 = Bg + (size_t)lrow        * K + lseg;
    const float* B1 = Bg + (size_t)(lrow + 64) * K + lseg;

    for (int k0 = 0; k0 < K; k0 += 16) {
        float4 a0 = *(const float4*)(A0 + k0);
        float4 a1 = *(const float4*)(A1 + k0);
        float4 b0 = *(const float4*)(B0 + k0);
        float4 b1 = *(const float4*)(B1 + k0);

        __syncthreads();   // previous iteration's compute done before overwrite
        As[lseg + 0][lrow]      = a0.x; As[lseg + 1][lrow]      = a0.y;
        As[lseg + 2][lrow]      = a0.z; As[lseg + 3][lrow]      = a0.w;
        As[lseg + 0][lrow + 64] = a1.x; As[lseg + 1][lrow + 64] = a1.y;
        As[lseg + 2][lrow + 64] = a1.z; As[lseg + 3][lrow + 64] = a1.w;
        Bs[lseg + 0][lrow]      = b0.x; Bs[lseg + 1][lrow]      = b0.y;
        Bs[lseg + 2][lrow]      = b0.z; Bs[lseg + 3][lrow]      = b0.w;
        Bs[lseg + 0][lrow + 64] = b1.x; Bs[lseg + 1][lrow + 64] = b1.y;
        Bs[lseg + 2][lrow + 64] = b1.z; Bs[lseg + 3][lrow + 64] = b1.w;
        __syncthreads();

#pragma unroll
        for (int kk = 0; kk < 16; kk++) {
            float4 av0 = *(const float4*)(&As[kk][ty * 4]);
            float4 av1 = *(const float4*)(&As[kk][ty * 4 + 64]);
            float4 bv0 = *(const float4*)(&Bs[kk][tx * 4]);
            float4 bv1 = *(const float4*)(&Bs[kk][tx * 4 + 64]);
            float a[8] = {av0.x, av0.y, av0.z, av0.w, av1.x, av1.y, av1.z, av1.w};
            float b[8] = {bv0.x, bv0.y, bv0.z, bv0.w, bv1.x, bv1.y, bv1.z, bv1.w};
#pragma unroll
            for (int i = 0; i < 8; i++)
#pragma unroll
                for (int j = 0; j < 8; j++)
                    acc[i][j] = fmaf(a[i], b[j], acc[i][j]);
        }
    }

#pragma unroll
    for (int i = 0; i < 8; i++) {
        int m = ty * 4 + (i & 3) + ((i >> 2) << 6);   // 4+4 split rows
        float4 c0 = make_float4(acc[i][0], acc[i][1], acc[i][2], acc[i][3]);
        float4 c1 = make_float4(acc[i][4], acc[i][5], acc[i][6], acc[i][7]);
        *(float4*)(Cg + (size_t)m * ldc + tx * 4)      = c0;
        *(float4*)(Cg + (size_t)m * ldc + tx * 4 + 64) = c1;
    }
}

// ---------------------------------------------------------------------------
// Fused QKV projection: one launch, grid (12, 32).
// N-blocks 0..7 -> q (ldc 1024), 8..9 -> k (ldc 256), 10..11 -> v (ldc 256).
// ---------------------------------------------------------------------------
__global__ void __launch_bounds__(256, 2)
qkv_kernel(const float* __restrict__ x,  const float* __restrict__ wq,
           const float* __restrict__ wk, const float* __restrict__ wv)
{
    const int nb = blockIdx.x;
    const int mb = blockIdx.y;
    const float* Bg;
    float* Cg;
    int ldc;
    if (nb < 8) {
        Bg  = wq + (size_t)nb * 128 * DIMK;
        Cg  = g_q + (size_t)mb * 128 * 1024 + nb * 128;
        ldc = 1024;
    } else if (nb < 10) {
        int t = nb - 8;
        Bg  = wk + (size_t)t * 128 * DIMK;
        Cg  = g_k + (size_t)mb * 128 * 256 + t * 128;
        ldc = 256;
    } else {
        int t = nb - 10;
        Bg  = wv + (size_t)t * 128 * DIMK;
        Cg  = g_v + (size_t)mb * 128 * 256 + t * 128;
        ldc = 256;
    }
    gemm128(x + (size_t)mb * 128 * DIMK, Bg, Cg, DIMK, ldc);
}

// ---------------------------------------------------------------------------
// Output projection: out = g_ao @ wo^T, grid (8, 32).
// ---------------------------------------------------------------------------
__global__ void __launch_bounds__(256, 2)
oproj_kernel(const float* __restrict__ wo, float* __restrict__ out)
{
    gemm128(g_ao + (size_t)blockIdx.y * 128 * 1024,
            wo   + (size_t)blockIdx.x * 128 * DIMK,
            out  + (size_t)blockIdx.y * 128 * 1024 + blockIdx.x * 128,
            DIMK, 1024);
}

// ---------------------------------------------------------------------------
// Per-head RMSNorm: one warp per (token, head) of 64 values.
// which==0 -> g_q (outScale folds in softmax 1/sqrt(64)), which==1 -> g_k.
// norm = rsqrt(mean(x^2) + 0.01); out = x * norm * w * outScale
// ---------------------------------------------------------------------------
__global__ void rmsnorm_kernel(const float* __restrict__ w, int which,
                               int total, float outScale)
{
    int wp = (blockIdx.x * blockDim.x + threadIdx.x) >> 5;
    if (wp >= total) return;
    int lane = threadIdx.x & 31;
    float* p = (which == 0 ? g_q : g_k) + (size_t)wp * 64 + lane * 2;
    float2 v = *(float2*)p;
    float ss = v.x * v.x + v.y * v.y;
#pragma unroll
    for (int o = 16; o > 0; o >>= 1) ss += __shfl_xor_sync(0xffffffffu, ss, o);
    float norm = rsqrtf(ss * (1.0f / 64.0f) + 0.01f) * outScale;
    float2 wv = *(const float2*)(w + lane * 2);
    v.x *= norm * wv.x;
    v.y *= norm * wv.y;
    *(float2*)p = v;
}

// ---------------------------------------------------------------------------
// Sliding-window ALiBi attention. WINDOW=16 => each query sees <=17 keys.
// One warp handles 4 consecutive queries of one (b,h): union key window
// [i0-16, i0+3] loaded once per j. Online softmax fully in registers.
// Each lane owns 2 of the 64 head dims; dot via 5x shfl_xor.
// q already carries the 1/sqrt(64) scale (folded in rmsnorm).
// ---------------------------------------------------------------------------
__global__ void attn_kernel()
{
    int gw   = (blockIdx.x * blockDim.x + threadIdx.x) >> 5;  // 0..16383
    int lane = threadIdx.x & 31;
    int b  = gw >> 13;               // 8192 warps per batch
    int h  = (gw >> 9) & 15;
    int i0 = (gw & 511) << 2;        // first of 4 queries
    int kvh = h & 3;                 // GQA: head h -> kv head h % 4

    float slope = exp2f(-0.5f * (float)(h + 1));   // ALiBi slope 2^{-(h+1)/2}

    const float* qp = g_q + ((size_t)(b * LSEQ + i0) * 1024) + h * 64 + lane * 2;
    float2 qv[4];
#pragma unroll
    for (int t = 0; t < 4; t++) qv[t] = *(const float2*)(qp + t * 1024);

    const float* kp = g_k + (size_t)b * LSEQ * 256 + kvh * 64 + lane * 2;
    const float* vp = g_v + (size_t)b * LSEQ * 256 + kvh * 64 + lane * 2;

    float m[4], l[4], ax[4], ay[4];
#pragma unroll
    for (int t = 0; t < 4; t++) { m[t] = -1e30f; l[t] = 0.f; ax[t] = 0.f; ay[t] = 0.f; }

    int jlo = i0 - 16; if (jlo < 0) jlo = 0;
    for (int j = jlo; j <= i0 + 3; j++) {
        float2 kk = *(const float2*)(kp + (size_t)j * 256);
        float2 vv = *(const float2*)(vp + (size_t)j * 256);
#pragma unroll
        for (int t = 0; t < 4; t++) {
            int i = i0 + t;
            if (j > i || j < i - 16) continue;   // warp-uniform predicate
            float s = qv[t].x * kk.x + qv[t].y * kk.y;
#pragma unroll
            for (int o = 16; o > 0; o >>= 1) s += __shfl_xor_sync(0xffffffffu, s, o);
            s += slope * (float)(j - i);         // ALiBi bias (<= 0)
            float mn = fmaxf(m[t], s);
            float c  = __expf(m[t] - mn);
            float p  = __expf(s - mn);
            l[t]  = l[t]  * c + p;
            ax[t] = ax[t] * c + p * vv.x;
            ay[t] = ay[t] * c + p * vv.y;
            m[t]  = mn;
        }
    }

    float* op = g_ao + ((size_t)(b * LSEQ + i0) * 1024) + h * 64 + lane * 2;
#pragma unroll
    for (int t = 0; t < 4; t++) {
        float inv = 1.0f / l[t];
        *(float2*)(op + t * 1024) = make_float2(ax[t] * inv, ay[t] * inv);
    }
}

// ---------------------------------------------------------------------------
// Launch sequence (graph-capturable: kernel launches only, default stream)
// Inputs: 0=x, 1=wq, 2=wk, 3=wv, 4=wo, 5=q_norm_w, 6=k_norm_w
// ---------------------------------------------------------------------------
extern "C" void kernel_launch(void* const* d_in, const int* in_sizes, int n_in,
                              void* d_out, int out_size)
{
    const float* x   = (const float*)d_in[0];
    const float* wq  = (const float*)d_in[1];
    const float* wk  = (const float*)d_in[2];
    const float* wv  = (const float*)d_in[3];
    const float* wo  = (const float*)d_in[4];
    const float* qnw = (const float*)d_in[5];
    const float* knw = (const float*)d_in[6];
    float* out = (float*)d_out;

    // 1) QKV projection (fused): grid (12, 32)
    qkv_kernel<<<dim3(12, 32), 256>>>(x, wq, wk, wv);

    // 2) RMSNorm q (folds attention scale 1/8) : 4096*16 warps
    rmsnorm_kernel<<<(TOK * HQ * 32) / 256, 256>>>(qnw, 0, TOK * HQ, 0.125f);

    // 3) RMSNorm k : 4096*4 warps
    rmsnorm_kernel<<<(TOK * HKV * 32) / 256, 256>>>(knw, 1, TOK * HKV, 1.0f);

    // 4) Sliding-window ALiBi attention: 16384 warps (4 queries each)
    attn_kernel<<<2048, 256>>>();

    // 5) Output projection: grid (8, 32)
    oproj_kernel<<<dim3(8, 32), 256>>>(wo, out);
}